// round 13
// baseline (speedup 1.0000x reference)
#include <cuda_runtime.h>

// ---------------- problem constants ----------------
#define B_    2
#define T_    2048
#define C_    1024
#define NH    16
#define NKV   8
#define HD    64
#define E_    8
#define H_    2048
#define NTOK  (B_*T_)        // 4096
#define TOPK  2
#define CAP   2048           // 2*NTOK*TOPK/E_
#define EPSF  1.1920928955078125e-07f

typedef unsigned short ushort_t;

// ---------------- scratch (device globals; no runtime alloc) ----------------
__device__ float g_xn [NTOK*C_];
__device__ float g_q  [NTOK*NH*HD];
__device__ float g_k  [NTOK*NKV*HD];
__device__ float g_v  [NTOK*NKV*HD];
__device__ float g_y  [NTOK*C_];
__device__ float g_x1 [NTOK*C_];
__device__ float g_xn2[NTOK*C_];
__device__ float g_bo [E_*CAP*C_];
__device__ int   g_tke[NTOK*TOPK];
__device__ float g_tkw[NTOK*TOPK];
__device__ int   g_rowsrc[E_*CAP];
__device__ int   g_entryrow[NTOK*TOPK];
__device__ int   g_me[E_];

// bf16 hi/lo split buffers
__device__ ushort_t s_xn_h [NTOK*C_],      s_xn_l [NTOK*C_];
__device__ ushort_t s_y_h  [NTOK*C_],      s_y_l  [NTOK*C_];
__device__ ushort_t s_xn2_h[NTOK*C_],      s_xn2_l[NTOK*C_];
__device__ ushort_t w_q_h [NH*HD*C_],      w_q_l [NH*HD*C_];
__device__ ushort_t w_k_h [NKV*HD*C_],     w_k_l [NKV*HD*C_];
__device__ ushort_t w_v_h [NKV*HD*C_],     w_v_l [NKV*HD*C_];
__device__ ushort_t w_p_h [C_*C_],         w_p_l [C_*C_];
__device__ ushort_t w_fc_h[E_*H_*C_],      w_fc_l[E_*H_*C_];
__device__ ushort_t w_pj_h[E_*C_*H_],      w_pj_l[E_*C_*H_];
__device__ ushort_t s_h_h [E_*CAP*H_],     s_h_l [E_*CAP*H_];

// ---------------- helpers ----------------
__device__ __forceinline__ void split2(float f0, float f1, unsigned &hi, unsigned &lo) {
    unsigned h;
    asm("cvt.rn.bf16x2.f32 %0, %1, %2;" : "=r"(h) : "f"(f1), "f"(f0));
    float h0 = __uint_as_float(h << 16);
    float h1 = __uint_as_float(h & 0xffff0000u);
    float r0 = f0 - h0;
    float r1 = f1 - h1;
    unsigned l;
    asm("cvt.rn.bf16x2.f32 %0, %1, %2;" : "=r"(l) : "f"(r1), "f"(r0));
    hi = h; lo = l;
}
__device__ __forceinline__ void mma_bf16(float* c, const unsigned* a, const unsigned* b) {
    asm volatile(
        "mma.sync.aligned.m16n8k16.row.col.f32.bf16.bf16.f32 "
        "{%0,%1,%2,%3},{%4,%5,%6,%7},{%8,%9},{%0,%1,%2,%3};"
        : "+f"(c[0]), "+f"(c[1]), "+f"(c[2]), "+f"(c[3])
        : "r"(a[0]), "r"(a[1]), "r"(a[2]), "r"(a[3]), "r"(b[0]), "r"(b[1]));
}
__device__ __forceinline__ void ldsm4(unsigned &r0, unsigned &r1, unsigned &r2, unsigned &r3,
                                      unsigned addr) {
    asm volatile("ldmatrix.sync.aligned.m8n8.x4.shared.b16 {%0,%1,%2,%3}, [%4];"
                 : "=r"(r0), "=r"(r1), "=r"(r2), "=r"(r3) : "r"(addr));
}

// ---------------- split: f32 -> bf16 hi/lo ----------------
__global__ __launch_bounds__(256) void split_kernel(const float* __restrict__ in,
                                                    unsigned* __restrict__ hi,
                                                    unsigned* __restrict__ lo, int n2) {
    int i = blockIdx.x*256 + threadIdx.x;
    if (i < n2) {
        float2 f = ((const float2*)in)[i];
        unsigned h, l;
        split2(f.x, f.y, h, l);
        hi[i] = h; lo[i] = l;
    }
}

// ---------------- RMS norm ----------------
__global__ __launch_bounds__(256) void rms_kernel(const float* __restrict__ x,
                                                  float* __restrict__ o) {
    int row = blockIdx.x;
    const float4* xr = (const float4*)(x + (long)row*C_);
    float4 v = xr[threadIdx.x];
    float ss = v.x*v.x + v.y*v.y + v.z*v.z + v.w*v.w;
    #pragma unroll
    for (int off = 16; off; off >>= 1) ss += __shfl_xor_sync(0xffffffffu, ss, off);
    __shared__ float sred[8];
    if ((threadIdx.x & 31) == 0) sred[threadIdx.x >> 5] = ss;
    __syncthreads();
    if (threadIdx.x == 0) {
        float t = 0.f;
        #pragma unroll
        for (int i = 0; i < 8; i++) t += sred[i];
        sred[0] = rsqrtf(t / (float)C_ + EPSF);
    }
    __syncthreads();
    float s = sred[0];
    v.x *= s; v.y *= s; v.z *= s; v.w *= s;
    ((float4*)(o + (long)row*C_))[threadIdx.x] = v;
}

// ---------------- bf16 hi/lo split-precision tensor GEMM (512 threads) ----------------
// C[m,n] = sum_k A[m,k]*B[n,k], split product hi*hi + hi*lo + lo*hi
// epi: 0 fp32 out, 1 fp32 out + Res, 2 relu(acc)^2 -> split bf16 out (Chi/Clo)
// BM=128, BN=128, BK=32, 16 warps (4x4, 32x32 warp tile), 3-stage cp.async, ldmatrix.
__global__ __launch_bounds__(512) void gemm_bf(
    const ushort_t* __restrict__ Ah, const ushort_t* __restrict__ Al, long sA,
    const ushort_t* __restrict__ Bh, const ushort_t* __restrict__ Bl, long sB,
    float* __restrict__ Cf, unsigned* __restrict__ Chi, unsigned* __restrict__ Clo, long sC,
    const float* __restrict__ Res,
    int M, int N, int K,
    const int* __restrict__ rowsrc, const int* __restrict__ mcounts, int epi)
{
    constexpr int BK = 32;
    int e  = blockIdx.z;
    int Mz = mcounts ? mcounts[e] : M;
    int m0 = blockIdx.y * 128;
    if (m0 >= Mz) return;
    int n0 = blockIdx.x * 128;

    const ushort_t* Ahb = Ah + (long)e * sA;
    const ushort_t* Alb = Al + (long)e * sA;
    const ushort_t* Bhb = Bh + (long)e * sB;
    const ushort_t* Blb = Bl + (long)e * sB;

    extern __shared__ ushort_t sm[];
    unsigned sbase = (unsigned)__cvta_generic_to_shared(sm);
    // stage layout (bytes): [Ahi 8K][Alo 8K][Bhi 8K][Blo 8K] = 32KB/stage, 3 stages

    int tid = threadIdx.x;
    int lr = tid >> 2, lc = tid & 3;     // loader: one row, one 16B chunk per tile

    long aoff; int sdst;
    {
        int gm = m0 + lr; if (gm >= Mz) gm = Mz - 1;
        int grow = rowsrc ? rowsrc[e*CAP + gm] : gm;
        aoff = (long)grow*K + lc*8;
        sdst = lr*64 + ((lc ^ ((lr>>1)&3)) << 4);
    }
    long boff = (long)(n0 + lr)*K + lc*8;

    auto load_tile = [&](int stage, int k0) {
        unsigned sb = sbase + stage*32768u;
        asm volatile("cp.async.cg.shared.global [%0], [%1], 16;"
                     :: "r"(sb + sdst),           "l"(Ahb + aoff + k0));
        asm volatile("cp.async.cg.shared.global [%0], [%1], 16;"
                     :: "r"(sb + 8192u + sdst),   "l"(Alb + aoff + k0));
        asm volatile("cp.async.cg.shared.global [%0], [%1], 16;"
                     :: "r"(sb + 16384u + sdst),  "l"(Bhb + boff + k0));
        asm volatile("cp.async.cg.shared.global [%0], [%1], 16;"
                     :: "r"(sb + 24576u + sdst),  "l"(Blb + boff + k0));
        asm volatile("cp.async.commit_group;");
    };

    int wid = tid >> 5, lane = tid & 31;
    int wm = wid >> 2, wn = wid & 3;     // 4 x 4 warps, warp tile 32m x 32n
    int g = lane >> 2, tig = lane & 3;

    // per-lane ldmatrix row bases
    int rA[2], rAx[2];
    #pragma unroll
    for (int i = 0; i < 2; i++) { rA[i] = wm*32 + i*16 + (lane & 15); rAx[i] = (rA[i]>>1)&3; }
    int chA = lane >> 4;                  // k-half for A
    int rB[2], rBx[2];
    #pragma unroll
    for (int jp = 0; jp < 2; jp++) {
        rB[jp]  = wn*32 + jp*16 + 8*(lane>>4) + (lane & 7);
        rBx[jp] = (rB[jp]>>1)&3;
    }
    int chB = (lane >> 3) & 1;            // k-half for B

    float acc[2][4][4];
    #pragma unroll
    for (int i = 0; i < 2; i++)
        #pragma unroll
        for (int j = 0; j < 4; j++)
            #pragma unroll
            for (int q = 0; q < 4; q++) acc[i][j][q] = 0.f;

    auto compute = [&](int stage) {
        unsigned sb = sbase + stage*32768u;
        #pragma unroll
        for (int kc = 0; kc < 2; kc++) {
            unsigned bh[4][2], bl[4][2];
            #pragma unroll
            for (int jp = 0; jp < 2; jp++) {
                unsigned addr = sb + 16384u + (unsigned)(rB[jp]*64 + (((kc*2 + chB) ^ rBx[jp]) << 4));
                ldsm4(bh[2*jp][0], bh[2*jp][1], bh[2*jp+1][0], bh[2*jp+1][1], addr);
                ldsm4(bl[2*jp][0], bl[2*jp][1], bl[2*jp+1][0], bl[2*jp+1][1], addr + 8192u);
            }
            #pragma unroll
            for (int i = 0; i < 2; i++) {
                unsigned addrA = sb + (unsigned)(rA[i]*64 + (((kc*2 + chA) ^ rAx[i]) << 4));
                unsigned ah[4], al[4];
                ldsm4(ah[0], ah[1], ah[2], ah[3], addrA);
                ldsm4(al[0], al[1], al[2], al[3], addrA + 8192u);
                #pragma unroll
                for (int j = 0; j < 4; j++) {
                    mma_bf16(acc[i][j], ah, bh[j]);
                    mma_bf16(acc[i][j], ah, bl[j]);
                    mma_bf16(acc[i][j], al, bh[j]);
                }
            }
        }
    };

    int KT = K / BK;
    load_tile(0, 0);
    load_tile(1, BK);
    for (int kt = 0; kt < KT; kt++) {
        if (kt + 2 < KT) {
            load_tile((kt + 2) % 3, (kt + 2)*BK);
            asm volatile("cp.async.wait_group 2;");
        } else {
            asm volatile("cp.async.wait_group 0;");
        }
        __syncthreads();
        compute(kt % 3);
        __syncthreads();
    }

    // epilogue
    #pragma unroll
    for (int i = 0; i < 2; i++) {
        int rm0 = m0 + wm*32 + i*16 + g;
        #pragma unroll
        for (int half = 0; half < 2; half++) {
            int rm = rm0 + half*8;
            if (rm < Mz) {
                #pragma unroll
                for (int j = 0; j < 4; j++) {
                    int col = n0 + wn*32 + j*8 + tig*2;
                    float v0 = acc[i][j][half*2 + 0];
                    float v1 = acc[i][j][half*2 + 1];
                    if (epi == 1) {
                        float2 rr = *(const float2*)&Res[(long)rm*N + col];
                        v0 += rr.x; v1 += rr.y;
                        *(float2*)&Cf[(long)e*sC + (long)rm*N + col] = make_float2(v0, v1);
                    } else if (epi == 2) {
                        v0 = fmaxf(v0, 0.f); v0 *= v0;
                        v1 = fmaxf(v1, 0.f); v1 *= v1;
                        unsigned h, l;
                        split2(v0, v1, h, l);
                        long idx = ((long)e*sC + (long)rm*N + col) >> 1;
                        Chi[idx] = h; Clo[idx] = l;
                    } else {
                        *(float2*)&Cf[(long)e*sC + (long)rm*N + col] = make_float2(v0, v1);
                    }
                }
            }
        }
    }
}

// ---------------- gate + v-update + RoPE + q/k RMS ----------------
__global__ __launch_bounds__(256) void gate_rope_kernel(
    const float* __restrict__ ve, const float* __restrict__ cosb,
    const float* __restrict__ sinb, const float* __restrict__ gw)
{
    int n = blockIdx.x;
    int tid = threadIdx.x, lane = tid & 31, w = tid >> 5;
    __shared__ float gs[8];
    float gsum = g_xn[(long)n*C_ + lane] * gw[w*32 + lane];
    #pragma unroll
    for (int off = 16; off; off >>= 1) gsum += __shfl_xor_sync(0xffffffffu, gsum, off);
    if (lane == 0) gs[w] = 2.f / (1.f + __expf(-gsum));
    __syncthreads();
    for (int idx = tid; idx < NKV*HD; idx += 256) {
        int kvh = idx >> 6;
        g_v[(long)n*(NKV*HD) + idx] += gs[kvh] * ve[(long)n*(NKV*HD) + idx];
    }
    int ts = n & (T_ - 1);
    float c = cosb[ts*32 + lane], s = sinb[ts*32 + lane];
    #pragma unroll
    for (int hh = 0; hh < 3; hh++) {
        float* p;
        if (hh == 0)      p = g_q + (long)n*(NH*HD)  + w*HD;
        else if (hh == 1) p = g_q + (long)n*(NH*HD)  + (w+8)*HD;
        else              p = g_k + (long)n*(NKV*HD) + w*HD;
        float x1 = p[lane], x2 = p[lane + 32];
        float o1 = x1*c + x2*s;
        float o2 = x2*c - x1*s;
        float ss = o1*o1 + o2*o2;
        #pragma unroll
        for (int off = 16; off; off >>= 1) ss += __shfl_xor_sync(0xffffffffu, ss, off);
        ss = __shfl_sync(0xffffffffu, ss, 0);
        float r = rsqrtf(ss / (float)HD + EPSF);
        p[lane]      = o1 * r;
        p[lane + 32] = o2 * r;
    }
}

// ---------------- sliding-window GQA attention ----------------
__global__ __launch_bounds__(128) void attn_kernel(const int* __restrict__ wptr) {
    int W = wptr[0];
    int b = blockIdx.z, h = blockIdx.y;
    int qi  = blockIdx.x * 128 + threadIdx.x;
    int tok = b * T_ + qi;
    int kvh = h >> 1;

    const float* qp = g_q + (long)tok*(NH*HD) + h*HD;
    float qr[HD];
    #pragma unroll
    for (int i = 0; i < 16; i++) {
        float4 t4 = ((const float4*)qp)[i];
        qr[4*i+0] = t4.x * 0.125f; qr[4*i+1] = t4.y * 0.125f;
        qr[4*i+2] = t4.z * 0.125f; qr[4*i+3] = t4.w * 0.125f;
    }
    float acc[HD];
    #pragma unroll
    for (int d = 0; d < HD; d++) acc[d] = 0.f;
    float mi = -1e30f, li = 0.f;

    __shared__ float Ks[32][HD];
    __shared__ float Vs[32][HD];
    __shared__ float Ss[128][33];

    int qb   = blockIdx.x * 128;
    int jblo = qb - W; if (jblo < 0) jblo = 0;
    jblo &= ~31;
    int jbhi = qb + 127;
    int myjlo = qi - W; if (myjlo < 0) myjlo = 0;

    for (int j0 = jblo; j0 <= jbhi; j0 += 32) {
        #pragma unroll
        for (int i = 0; i < 4; i++) {
            int idx = threadIdx.x + i*128;
            int r = idx >> 4, c4 = idx & 15;
            long off = (long)(b*T_ + j0 + r) * (NKV*HD) + kvh*HD + c4*4;
            ((float4*)&Ks[r][0])[c4] = *(const float4*)(g_k + off);
            ((float4*)&Vs[r][0])[c4] = *(const float4*)(g_v + off);
        }
        __syncthreads();
        int lo = j0 > myjlo ? j0 : myjlo;
        int hi = (j0 + 31) < qi ? (j0 + 31) : qi;
        if (lo <= hi) {
            float mloc = -1e30f;
            for (int j = lo; j <= hi; j++) {
                const float4* kr = (const float4*)&Ks[j - j0][0];
                float s = 0.f;
                #pragma unroll
                for (int d4 = 0; d4 < 16; d4++) {
                    float4 kv = kr[d4];
                    s = fmaf(qr[4*d4+0], kv.x, s);
                    s = fmaf(qr[4*d4+1], kv.y, s);
                    s = fmaf(qr[4*d4+2], kv.z, s);
                    s = fmaf(qr[4*d4+3], kv.w, s);
                }
                Ss[threadIdx.x][j - j0] = s;
                mloc = s > mloc ? s : mloc;
            }
            float mnew = mi > mloc ? mi : mloc;
            float corr = __expf(mi - mnew);
            li *= corr;
            #pragma unroll
            for (int d = 0; d < HD; d++) acc[d] *= corr;
            for (int j = lo; j <= hi; j++) {
                float p = __expf(Ss[threadIdx.x][j - j0] - mnew);
                li += p;
                const float4* vr = (const float4*)&Vs[j - j0][0];
                #pragma unroll
                for (int d4 = 0; d4 < 16; d4++) {
                    float4 vv = vr[d4];
                    acc[4*d4+0] = fmaf(p, vv.x, acc[4*d4+0]);
                    acc[4*d4+1] = fmaf(p, vv.y, acc[4*d4+1]);
                    acc[4*d4+2] = fmaf(p, vv.z, acc[4*d4+2]);
                    acc[4*d4+3] = fmaf(p, vv.w, acc[4*d4+3]);
                }
            }
            mi = mnew;
        }
        __syncthreads();
    }
    float inv = 1.f / li;
    float* yp = g_y + (long)tok*C_ + h*HD;
    #pragma unroll
    for (int i = 0; i < 16; i++) {
        float4 o4;
        o4.x = acc[4*i+0]*inv; o4.y = acc[4*i+1]*inv;
        o4.z = acc[4*i+2]*inv; o4.w = acc[4*i+3]*inv;
        ((float4*)yp)[i] = o4;
    }
}

// ---------------- router: softmax over 8 experts + top-2 ----------------
__global__ __launch_bounds__(256) void router_kernel(const float* __restrict__ rww,
                                                     float* __restrict__ out_rw) {
    int n = blockIdx.x;
    int lane = threadIdx.x & 31, w = threadIdx.x >> 5;
    const float* xr = g_xn2 + (long)n*C_;
    const float* wr = rww + (long)w*C_;
    float sum = 0.f;
    for (int kk = lane; kk < C_; kk += 32) sum = fmaf(xr[kk], wr[kk], sum);
    #pragma unroll
    for (int off = 16; off; off >>= 1) sum += __shfl_xor_sync(0xffffffffu, sum, off);
    __shared__ float lg[8];
    if (lane == 0) lg[w] = sum;
    __syncthreads();
    if (threadIdx.x == 0) {
        float mx = lg[0];
        #pragma unroll
        for (int e = 1; e < 8; e++) mx = lg[e] > mx ? lg[e] : mx;
        float ex[8], s = 0.f;
        #pragma unroll
        for (int e = 0; e < 8; e++) { ex[e] = __expf(lg[e] - mx); s += ex[e]; }
        float inv = 1.f / s;
        float rw[8];
        #pragma unroll
        for (int e = 0; e < 8; e++) { rw[e] = ex[e] * inv; out_rw[(long)n*E_ + e] = rw[e]; }
        int i0 = 0;
        #pragma unroll
        for (int e = 1; e < 8; e++) if (rw[e] > rw[i0]) i0 = e;
        int i1 = (i0 == 0) ? 1 : 0;
        #pragma unroll
        for (int e = 0; e < 8; e++) if (e != i0 && rw[e] > rw[i1]) i1 = e;
        float w0 = rw[i0], w1 = rw[i1];
        float d = w0 + w1 + 1e-10f;
        g_tke[2*n]   = i0; g_tke[2*n+1] = i1;
        g_tkw[2*n]   = w0 / d; g_tkw[2*n+1] = w1 / d;
    }
}

// ---------------- stable expert dispatch (single block) ----------------
__global__ __launch_bounds__(256) void route_kernel() {
    __shared__ int cnts[256][8];
    int tid = threadIdx.x;
    int c[8];
    #pragma unroll
    for (int e = 0; e < 8; e++) c[e] = 0;
    int base = tid * 32;
    for (int i = 0; i < 32; i++) c[g_tke[base + i]]++;
    #pragma unroll
    for (int e = 0; e < 8; e++) cnts[tid][e] = c[e];
    __syncthreads();
    if (tid < 8) {
        int run = 0;
        for (int t = 0; t < 256; t++) { int tmp = cnts[t][tid]; cnts[t][tid] = run; run += tmp; }
        g_me[tid] = run < CAP ? run : CAP;
    }
    __syncthreads();
    #pragma unroll
    for (int e = 0; e < 8; e++) c[e] = cnts[tid][e];
    for (int i = 0; i < 32; i++) {
        int gi = base + i;
        int e = g_tke[gi];
        int pos = c[e]++;
        if (pos < CAP) {
            int row = e * CAP + pos;
            g_rowsrc[row]   = gi >> 1;
            g_entryrow[gi]  = row;
        } else {
            g_entryrow[gi] = -1;
        }
    }
}

// ---------------- combine ----------------
__global__ __launch_bounds__(256) void combine_kernel(float* __restrict__ outx) {
    int n = blockIdx.x, tid = threadIdx.x;
    float4 r = ((const float4*)(g_x1 + (long)n*C_))[tid];
    #pragma unroll
    for (int s = 0; s < 2; s++) {
        int row = g_entryrow[n*2 + s];
        if (row >= 0) {
            float ww = g_tkw[n*2 + s];
            float4 bv = ((const float4*)(g_bo + (long)row*C_))[tid];
            r.x = fmaf(ww, bv.x, r.x); r.y = fmaf(ww, bv.y, r.y);
            r.z = fmaf(ww, bv.z, r.z); r.w = fmaf(ww, bv.w, r.w);
        }
    }
    ((float4*)(outx + (long)n*C_))[tid] = r;
}

// ---------------- host launcher ----------------
static inline void do_split(const float* src, void* hi, void* lo, long nelem) {
    int n2 = (int)(nelem >> 1);
    split_kernel<<<(n2 + 255)/256, 256>>>(src, (unsigned*)hi, (unsigned*)lo, n2);
}

extern "C" void kernel_launch(void* const* d_in, const int* in_sizes, int n_in,
                              void* d_out, int out_size) {
    const float* x    = (const float*)d_in[0];
    const float* ve   = (const float*)d_in[1];
    const float* cosb = (const float*)d_in[2];
    const float* sinb = (const float*)d_in[3];
    const float* cqw  = (const float*)d_in[4];
    const float* ckw  = (const float*)d_in[5];
    const float* cvw  = (const float*)d_in[6];
    const float* cpw  = (const float*)d_in[7];
    const float* gw   = (const float*)d_in[8];
    const float* rww  = (const float*)d_in[9];
    const float* fcw  = (const float*)d_in[10];
    const float* pjw  = (const float*)d_in[11];
    const int*   wptr = (const int*)d_in[12];
    float* out = (float*)d_out;

    float *xn, *q, *k, *v, *y, *x1, *xn2, *bo;
    int *rowsrc, *me;
    cudaGetSymbolAddress((void**)&xn,  g_xn);
    cudaGetSymbolAddress((void**)&q,   g_q);
    cudaGetSymbolAddress((void**)&k,   g_k);
    cudaGetSymbolAddress((void**)&v,   g_v);
    cudaGetSymbolAddress((void**)&y,   g_y);
    cudaGetSymbolAddress((void**)&x1,  g_x1);
    cudaGetSymbolAddress((void**)&xn2, g_xn2);
    cudaGetSymbolAddress((void**)&bo,  g_bo);
    cudaGetSymbolAddress((void**)&rowsrc, g_rowsrc);
    cudaGetSymbolAddress((void**)&me,     g_me);

    void *xnh,*xnl, *yh,*yl, *xn2h,*xn2l;
    void *wqh,*wql, *wkh,*wkl, *wvh,*wvl, *wph,*wpl, *wfh,*wfl, *wjh,*wjl, *hh,*hl;
    cudaGetSymbolAddress(&xnh, s_xn_h);   cudaGetSymbolAddress(&xnl, s_xn_l);
    cudaGetSymbolAddress(&yh,  s_y_h);    cudaGetSymbolAddress(&yl,  s_y_l);
    cudaGetSymbolAddress(&xn2h,s_xn2_h);  cudaGetSymbolAddress(&xn2l,s_xn2_l);
    cudaGetSymbolAddress(&wqh, w_q_h);    cudaGetSymbolAddress(&wql, w_q_l);
    cudaGetSymbolAddress(&wkh, w_k_h);    cudaGetSymbolAddress(&wkl, w_k_l);
    cudaGetSymbolAddress(&wvh, w_v_h);    cudaGetSymbolAddress(&wvl, w_v_l);
    cudaGetSymbolAddress(&wph, w_p_h);    cudaGetSymbolAddress(&wpl, w_p_l);
    cudaGetSymbolAddress(&wfh, w_fc_h);   cudaGetSymbolAddress(&wfl, w_fc_l);
    cudaGetSymbolAddress(&wjh, w_pj_h);   cudaGetSymbolAddress(&wjl, w_pj_l);
    cudaGetSymbolAddress(&hh,  s_h_h);    cudaGetSymbolAddress(&hl,  s_h_l);

    const int SMEM = 3*32768;  // 96KB
    cudaFuncSetAttribute(gemm_bf, cudaFuncAttributeMaxDynamicSharedMemorySize, SMEM);

    typedef const ushort_t* cus;

    // weight splits (independent of data flow)
    do_split(cqw, wqh, wql, (long)NH*HD*C_);
    do_split(ckw, wkh, wkl, (long)NKV*HD*C_);
    do_split(cvw, wvh, wvl, (long)NKV*HD*C_);
    do_split(cpw, wph, wpl, (long)C_*C_);
    do_split(fcw, wfh, wfl, (long)E_*H_*C_);
    do_split(pjw, wjh, wjl, (long)E_*C_*H_);

    // 1) xn = rms(x); split
    rms_kernel<<<NTOK, 256>>>(x, xn);
    do_split(xn, xnh, xnl, (long)NTOK*C_);

    // 2) q/k/v projections
    gemm_bf<<<dim3(NH*HD/128,  NTOK/128, 1), 512, SMEM>>>(
        (cus)xnh, (cus)xnl, 0, (cus)wqh, (cus)wql, 0,
        q, nullptr, nullptr, 0, nullptr, NTOK, NH*HD, C_, nullptr, nullptr, 0);
    gemm_bf<<<dim3(NKV*HD/128, NTOK/128, 1), 512, SMEM>>>(
        (cus)xnh, (cus)xnl, 0, (cus)wkh, (cus)wkl, 0,
        k, nullptr, nullptr, 0, nullptr, NTOK, NKV*HD, C_, nullptr, nullptr, 0);
    gemm_bf<<<dim3(NKV*HD/128, NTOK/128, 1), 512, SMEM>>>(
        (cus)xnh, (cus)xnl, 0, (cus)wvh, (cus)wvl, 0,
        v, nullptr, nullptr, 0, nullptr, NTOK, NKV*HD, C_, nullptr, nullptr, 0);

    // 3) gate + v update + rope + q/k rms
    gate_rope_kernel<<<NTOK, 256>>>(ve, cosb, sinb, gw);
    // 4) attention
    attn_kernel<<<dim3(T_/128, NH, B_), 128>>>(wptr);
    // 5) x1 = x + y @ c_proj^T
    do_split(y, yh, yl, (long)NTOK*C_);
    gemm_bf<<<dim3(C_/128, NTOK/128, 1), 512, SMEM>>>(
        (cus)yh, (cus)yl, 0, (cus)wph, (cus)wpl, 0,
        x1, nullptr, nullptr, 0, x, NTOK, C_, C_, nullptr, nullptr, 1);
    // 6) xn2 = rms(x1); split
    rms_kernel<<<NTOK, 256>>>(x1, xn2);
    do_split(xn2, xn2h, xn2l, (long)NTOK*C_);
    // 7) router softmax + top-2 (fp32 exact; writes rw output region)
    router_kernel<<<NTOK, 256>>>(rww, out + (long)NTOK * C_);
    // 8) stable dispatch
    route_kernel<<<1, 256>>>();
    // 9) h = relu(xn2[gather] @ fc_w[e]^T)^2  -> split bf16 out
    gemm_bf<<<dim3(H_/128, CAP/128, E_), 512, SMEM>>>(
        (cus)xn2h, (cus)xn2l, 0, (cus)wfh, (cus)wfl, (long)H_*C_,
        nullptr, (unsigned*)hh, (unsigned*)hl, (long)CAP*H_, nullptr,
        CAP, H_, C_, rowsrc, me, 2);
    // 10) bo = h @ proj_w[e]^T
    gemm_bf<<<dim3(C_/128, CAP/128, E_), 512, SMEM>>>(
        (cus)hh, (cus)hl, (long)CAP*H_, (cus)wjh, (cus)wjl, (long)C_*H_,
        bo, nullptr, nullptr, (long)CAP*C_, nullptr,
        CAP, C_, H_, nullptr, me, 0);
    // 11) final combine -> x output region
    combine_kernel<<<NTOK, 256>>>(out);
}

// round 16
// speedup vs baseline: 1.6686x; 1.6686x over previous
#include <cuda_runtime.h>

// ---------------- problem constants ----------------
#define B_    2
#define T_    2048
#define C_    1024
#define NH    16
#define NKV   8
#define HD    64
#define E_    8
#define H_    2048
#define NTOK  (B_*T_)        // 4096
#define TOPK  2
#define CAP   2048           // 2*NTOK*TOPK/E_
#define EPSF  1.1920928955078125e-07f
#define QS    2048           // fused qkv row stride (1024 q + 512 k + 512 v)

typedef unsigned short ushort_t;

// ---------------- scratch (device globals; no runtime alloc) ----------------
__device__ float g_xn [NTOK*C_];
__device__ float g_qkv[NTOK*QS];
__device__ float g_y  [NTOK*C_];
__device__ float g_x1 [NTOK*C_];
__device__ float g_xn2[NTOK*C_];
__device__ float g_bo [E_*CAP*C_];
__device__ int   g_tke[NTOK*TOPK];
__device__ float g_tkw[NTOK*TOPK];
__device__ int   g_rowsrc[E_*CAP];
__device__ int   g_entryrow[NTOK*TOPK];
__device__ int   g_me[E_];

// bf16 hi/lo split buffers
__device__ ushort_t s_xn_h [NTOK*C_],      s_xn_l [NTOK*C_];
__device__ ushort_t s_y_h  [NTOK*C_],      s_y_l  [NTOK*C_];
__device__ ushort_t s_xn2_h[NTOK*C_],      s_xn2_l[NTOK*C_];
__device__ ushort_t w_qkv_h[QS*C_],        w_qkv_l[QS*C_];
__device__ ushort_t w_p_h [C_*C_],         w_p_l [C_*C_];
__device__ ushort_t w_fc_h[E_*H_*C_],      w_fc_l[E_*H_*C_];
__device__ ushort_t w_pj_h[E_*C_*H_],      w_pj_l[E_*C_*H_];
__device__ ushort_t s_h_h [E_*CAP*H_],     s_h_l [E_*CAP*H_];

// ---------------- helpers ----------------
__device__ __forceinline__ void split2(float f0, float f1, unsigned &hi, unsigned &lo) {
    unsigned h;
    asm("cvt.rn.bf16x2.f32 %0, %1, %2;" : "=r"(h) : "f"(f1), "f"(f0));
    float h0 = __uint_as_float(h << 16);
    float h1 = __uint_as_float(h & 0xffff0000u);
    float r0 = f0 - h0;
    float r1 = f1 - h1;
    unsigned l;
    asm("cvt.rn.bf16x2.f32 %0, %1, %2;" : "=r"(l) : "f"(r1), "f"(r0));
    hi = h; lo = l;
}
__device__ __forceinline__ void mma_bf16(float* c, const unsigned* a, const unsigned* b) {
    asm volatile(
        "mma.sync.aligned.m16n8k16.row.col.f32.bf16.bf16.f32 "
        "{%0,%1,%2,%3},{%4,%5,%6,%7},{%8,%9},{%0,%1,%2,%3};"
        : "+f"(c[0]), "+f"(c[1]), "+f"(c[2]), "+f"(c[3])
        : "r"(a[0]), "r"(a[1]), "r"(a[2]), "r"(a[3]), "r"(b[0]), "r"(b[1]));
}
__device__ __forceinline__ void ldsm4(unsigned &r0, unsigned &r1, unsigned &r2, unsigned &r3,
                                      unsigned addr) {
    asm volatile("ldmatrix.sync.aligned.m8n8.x4.shared.b16 {%0,%1,%2,%3}, [%4];"
                 : "=r"(r0), "=r"(r1), "=r"(r2), "=r"(r3) : "r"(addr));
}

// ---------------- split: f32 -> bf16 hi/lo ----------------
__global__ __launch_bounds__(256) void split_kernel(const float* __restrict__ in,
                                                    unsigned* __restrict__ hi,
                                                    unsigned* __restrict__ lo, int n2) {
    int i = blockIdx.x*256 + threadIdx.x;
    if (i < n2) {
        float2 f = ((const float2*)in)[i];
        unsigned h, l;
        split2(f.x, f.y, h, l);
        hi[i] = h; lo[i] = l;
    }
}

// ---------------- RMS norm ----------------
__global__ __launch_bounds__(256) void rms_kernel(const float* __restrict__ x,
                                                  float* __restrict__ o) {
    int row = blockIdx.x;
    const float4* xr = (const float4*)(x + (long)row*C_);
    float4 v = xr[threadIdx.x];
    float ss = v.x*v.x + v.y*v.y + v.z*v.z + v.w*v.w;
    #pragma unroll
    for (int off = 16; off; off >>= 1) ss += __shfl_xor_sync(0xffffffffu, ss, off);
    __shared__ float sred[8];
    if ((threadIdx.x & 31) == 0) sred[threadIdx.x >> 5] = ss;
    __syncthreads();
    if (threadIdx.x == 0) {
        float t = 0.f;
        #pragma unroll
        for (int i = 0; i < 8; i++) t += sred[i];
        sred[0] = rsqrtf(t / (float)C_ + EPSF);
    }
    __syncthreads();
    float s = sred[0];
    v.x *= s; v.y *= s; v.z *= s; v.w *= s;
    ((float4*)(o + (long)row*C_))[threadIdx.x] = v;
}

// ---------------- bf16 hi/lo split-precision tensor GEMM ----------------
// C[m,n] = sum_k A[m,k]*B[n,k], split product hi*hi + hi*lo + lo*hi
// epi: 0 fp32 out, 1 fp32 out + Res, 2 relu(acc)^2 -> split bf16 out (Chi/Clo)
// BM=128, BN=256, BK=32, 256 threads (8 warps 2x4, warp tile 64x64),
// 3-stage cp.async, ldmatrix fragments.
__global__ __launch_bounds__(256, 1) void gemm_bf(
    const ushort_t* __restrict__ Ah, const ushort_t* __restrict__ Al, long sA,
    const ushort_t* __restrict__ Bh, const ushort_t* __restrict__ Bl, long sB,
    float* __restrict__ Cf, unsigned* __restrict__ Chi, unsigned* __restrict__ Clo, long sC,
    const float* __restrict__ Res,
    int M, int N, int K,
    const int* __restrict__ rowsrc, const int* __restrict__ mcounts, int epi)
{
    constexpr int BK = 32;
    constexpr unsigned STG = 49152u;   // stage bytes: Ahi 8K | Alo 8K | Bhi 16K | Blo 16K
    int e  = blockIdx.z;
    int Mz = mcounts ? mcounts[e] : M;
    int m0 = blockIdx.y * 128;
    if (m0 >= Mz) return;
    int n0 = blockIdx.x * 256;

    const ushort_t* Ahb = Ah + (long)e * sA;
    const ushort_t* Alb = Al + (long)e * sA;
    const ushort_t* Bhb = Bh + (long)e * sB;
    const ushort_t* Blb = Bl + (long)e * sB;

    extern __shared__ ushort_t sm[];
    unsigned sbase = (unsigned)__cvta_generic_to_shared(sm);

    int tid = threadIdx.x;
    int lr = tid >> 2, lc = tid & 3;     // row base 0..63, 16B chunk 0..3

    long aoff[2]; int adst[2];
    #pragma unroll
    for (int t = 0; t < 2; t++) {
        int r  = lr + 64*t;
        int gm = m0 + r; if (gm >= Mz) gm = Mz - 1;
        int grow = rowsrc ? rowsrc[e*CAP + gm] : gm;
        aoff[t] = (long)grow*K + lc*8;
        adst[t] = r*64 + ((lc ^ ((r>>1)&3)) << 4);
    }
    long boff[4]; int bdst[4];
    #pragma unroll
    for (int t = 0; t < 4; t++) {
        int r = lr + 64*t;
        boff[t] = (long)(n0 + r)*K + lc*8;
        bdst[t] = r*64 + ((lc ^ ((r>>1)&3)) << 4);
    }

    auto load_tile = [&](int stage, int k0) {
        unsigned sb = sbase + stage*STG;
        #pragma unroll
        for (int t = 0; t < 2; t++) {
            asm volatile("cp.async.cg.shared.global [%0], [%1], 16;"
                         :: "r"(sb + adst[t]),          "l"(Ahb + aoff[t] + k0));
            asm volatile("cp.async.cg.shared.global [%0], [%1], 16;"
                         :: "r"(sb + 8192u + adst[t]),  "l"(Alb + aoff[t] + k0));
        }
        #pragma unroll
        for (int t = 0; t < 4; t++) {
            asm volatile("cp.async.cg.shared.global [%0], [%1], 16;"
                         :: "r"(sb + 16384u + bdst[t]), "l"(Bhb + boff[t] + k0));
            asm volatile("cp.async.cg.shared.global [%0], [%1], 16;"
                         :: "r"(sb + 32768u + bdst[t]), "l"(Blb + boff[t] + k0));
        }
        asm volatile("cp.async.commit_group;");
    };

    int wid = tid >> 5, lane = tid & 31;
    int wm = wid >> 2, wn = wid & 3;     // 2 x 4 warps, warp tile 64m x 64n
    int g = lane >> 2, tig = lane & 3;

    // per-lane ldmatrix row bases
    int rA[4], rAx[4];
    #pragma unroll
    for (int i = 0; i < 4; i++) { rA[i] = wm*64 + i*16 + (lane & 15); rAx[i] = (rA[i]>>1)&3; }
    int chA = lane >> 4;                  // k-half for A
    int rB[4], rBx[4];
    #pragma unroll
    for (int jp = 0; jp < 4; jp++) {
        rB[jp]  = wn*64 + jp*16 + 8*(lane>>4) + (lane & 7);
        rBx[jp] = (rB[jp]>>1)&3;
    }
    int chB = (lane >> 3) & 1;            // k-half for B

    float acc[4][8][4];
    #pragma unroll
    for (int i = 0; i < 4; i++)
        #pragma unroll
        for (int j = 0; j < 8; j++)
            #pragma unroll
            for (int q = 0; q < 4; q++) acc[i][j][q] = 0.f;

    auto compute = [&](int stage) {
        unsigned sb = sbase + stage*STG;
        #pragma unroll
        for (int kc = 0; kc < 2; kc++) {
            unsigned bh[8][2], bl[8][2];
            #pragma unroll
            for (int jp = 0; jp < 4; jp++) {
                unsigned addr = sb + 16384u + (unsigned)(rB[jp]*64 + (((kc*2 + chB) ^ rBx[jp]) << 4));
                ldsm4(bh[2*jp][0], bh[2*jp][1], bh[2*jp+1][0], bh[2*jp+1][1], addr);
                ldsm4(bl[2*jp][0], bl[2*jp][1], bl[2*jp+1][0], bl[2*jp+1][1], addr + 16384u);
            }
            #pragma unroll
            for (int i = 0; i < 4; i++) {
                unsigned addrA = sb + (unsigned)(rA[i]*64 + (((kc*2 + chA) ^ rAx[i]) << 4));
                unsigned ah[4], al[4];
                ldsm4(ah[0], ah[1], ah[2], ah[3], addrA);
                ldsm4(al[0], al[1], al[2], al[3], addrA + 8192u);
                #pragma unroll
                for (int j = 0; j < 8; j++) {
                    mma_bf16(acc[i][j], ah, bh[j]);
                    mma_bf16(acc[i][j], ah, bl[j]);
                    mma_bf16(acc[i][j], al, bh[j]);
                }
            }
        }
    };

    int KT = K / BK;
    load_tile(0, 0);
    load_tile(1, BK);
    for (int kt = 0; kt < KT; kt++) {
        if (kt + 2 < KT) {
            load_tile((kt + 2) % 3, (kt + 2)*BK);
            asm volatile("cp.async.wait_group 2;");
        } else {
            asm volatile("cp.async.wait_group 0;");
        }
        __syncthreads();
        compute(kt % 3);
        __syncthreads();
    }

    // epilogue
    #pragma unroll
    for (int i = 0; i < 4; i++) {
        int rm0 = m0 + wm*64 + i*16 + g;
        #pragma unroll
        for (int half = 0; half < 2; half++) {
            int rm = rm0 + half*8;
            if (rm < Mz) {
                #pragma unroll
                for (int j = 0; j < 8; j++) {
                    int col = n0 + wn*64 + j*8 + tig*2;
                    float v0 = acc[i][j][half*2 + 0];
                    float v1 = acc[i][j][half*2 + 1];
                    if (epi == 1) {
                        float2 rr = *(const float2*)&Res[(long)rm*N + col];
                        v0 += rr.x; v1 += rr.y;
                        *(float2*)&Cf[(long)e*sC + (long)rm*N + col] = make_float2(v0, v1);
                    } else if (epi == 2) {
                        v0 = fmaxf(v0, 0.f); v0 *= v0;
                        v1 = fmaxf(v1, 0.f); v1 *= v1;
                        unsigned h, l;
                        split2(v0, v1, h, l);
                        long idx = ((long)e*sC + (long)rm*N + col) >> 1;
                        Chi[idx] = h; Clo[idx] = l;
                    } else {
                        *(float2*)&Cf[(long)e*sC + (long)rm*N + col] = make_float2(v0, v1);
                    }
                }
            }
        }
    }
}

// ---------------- gate + v-update + RoPE + q/k RMS (fused qkv layout) ----------------
__global__ __launch_bounds__(256) void gate_rope_kernel(
    const float* __restrict__ ve, const float* __restrict__ cosb,
    const float* __restrict__ sinb, const float* __restrict__ gw)
{
    int n = blockIdx.x;
    int tid = threadIdx.x, lane = tid & 31, w = tid >> 5;
    __shared__ float gs[8];
    float gsum = g_xn[(long)n*C_ + lane] * gw[w*32 + lane];
    #pragma unroll
    for (int off = 16; off; off >>= 1) gsum += __shfl_xor_sync(0xffffffffu, gsum, off);
    if (lane == 0) gs[w] = 2.f / (1.f + __expf(-gsum));
    __syncthreads();
    for (int idx = tid; idx < NKV*HD; idx += 256) {
        int kvh = idx >> 6;
        g_qkv[(long)n*QS + 1536 + idx] += gs[kvh] * ve[(long)n*(NKV*HD) + idx];
    }
    int ts = n & (T_ - 1);
    float c = cosb[ts*32 + lane], s = sinb[ts*32 + lane];
    #pragma unroll
    for (int hh = 0; hh < 3; hh++) {
        float* p;
        if (hh == 0)      p = g_qkv + (long)n*QS + w*HD;
        else if (hh == 1) p = g_qkv + (long)n*QS + (w+8)*HD;
        else              p = g_qkv + (long)n*QS + 1024 + w*HD;
        float x1 = p[lane], x2 = p[lane + 32];
        float o1 = x1*c + x2*s;
        float o2 = x2*c - x1*s;
        float ss = o1*o1 + o2*o2;
        #pragma unroll
        for (int off = 16; off; off >>= 1) ss += __shfl_xor_sync(0xffffffffu, ss, off);
        ss = __shfl_sync(0xffffffffu, ss, 0);
        float r = rsqrtf(ss / (float)HD + EPSF);
        p[lane]      = o1 * r;
        p[lane + 32] = o2 * r;
    }
}

// ---------------- sliding-window GQA attention (fused qkv layout) ----------------
__global__ __launch_bounds__(128) void attn_kernel(const int* __restrict__ wptr) {
    int W = wptr[0];
    int b = blockIdx.z, h = blockIdx.y;
    int qi  = blockIdx.x * 128 + threadIdx.x;
    int tok = b * T_ + qi;
    int kvh = h >> 1;

    const float* qp = g_qkv + (long)tok*QS + h*HD;
    float qr[HD];
    #pragma unroll
    for (int i = 0; i < 16; i++) {
        float4 t4 = ((const float4*)qp)[i];
        qr[4*i+0] = t4.x * 0.125f; qr[4*i+1] = t4.y * 0.125f;
        qr[4*i+2] = t4.z * 0.125f; qr[4*i+3] = t4.w * 0.125f;
    }
    float acc[HD];
    #pragma unroll
    for (int d = 0; d < HD; d++) acc[d] = 0.f;
    float mi = -1e30f, li = 0.f;

    __shared__ float Ks[32][HD];
    __shared__ float Vs[32][HD];
    __shared__ float Ss[128][33];

    int qb   = blockIdx.x * 128;
    int jblo = qb - W; if (jblo < 0) jblo = 0;
    jblo &= ~31;
    int jbhi = qb + 127;
    int myjlo = qi - W; if (myjlo < 0) myjlo = 0;

    for (int j0 = jblo; j0 <= jbhi; j0 += 32) {
        #pragma unroll
        for (int i = 0; i < 4; i++) {
            int idx = threadIdx.x + i*128;
            int r = idx >> 4, c4 = idx & 15;
            long off = (long)(b*T_ + j0 + r) * QS + 1024 + kvh*HD + c4*4;
            ((float4*)&Ks[r][0])[c4] = *(const float4*)(g_qkv + off);
            ((float4*)&Vs[r][0])[c4] = *(const float4*)(g_qkv + off + 512);
        }
        __syncthreads();
        int lo = j0 > myjlo ? j0 : myjlo;
        int hi = (j0 + 31) < qi ? (j0 + 31) : qi;
        if (lo <= hi) {
            float mloc = -1e30f;
            for (int j = lo; j <= hi; j++) {
                const float4* kr = (const float4*)&Ks[j - j0][0];
                float s = 0.f;
                #pragma unroll
                for (int d4 = 0; d4 < 16; d4++) {
                    float4 kv = kr[d4];
                    s = fmaf(qr[4*d4+0], kv.x, s);
                    s = fmaf(qr[4*d4+1], kv.y, s);
                    s = fmaf(qr[4*d4+2], kv.z, s);
                    s = fmaf(qr[4*d4+3], kv.w, s);
                }
                Ss[threadIdx.x][j - j0] = s;
                mloc = s > mloc ? s : mloc;
            }
            float mnew = mi > mloc ? mi : mloc;
            float corr = __expf(mi - mnew);
            li *= corr;
            #pragma unroll
            for (int d = 0; d < HD; d++) acc[d] *= corr;
            for (int j = lo; j <= hi; j++) {
                float p = __expf(Ss[threadIdx.x][j - j0] - mnew);
                li += p;
                const float4* vr = (const float4*)&Vs[j - j0][0];
                #pragma unroll
                for (int d4 = 0; d4 < 16; d4++) {
                    float4 vv = vr[d4];
                    acc[4*d4+0] = fmaf(p, vv.x, acc[4*d4+0]);
                    acc[4*d4+1] = fmaf(p, vv.y, acc[4*d4+1]);
                    acc[4*d4+2] = fmaf(p, vv.z, acc[4*d4+2]);
                    acc[4*d4+3] = fmaf(p, vv.w, acc[4*d4+3]);
                }
            }
            mi = mnew;
        }
        __syncthreads();
    }
    float inv = 1.f / li;
    float* yp = g_y + (long)tok*C_ + h*HD;
    #pragma unroll
    for (int i = 0; i < 16; i++) {
        float4 o4;
        o4.x = acc[4*i+0]*inv; o4.y = acc[4*i+1]*inv;
        o4.z = acc[4*i+2]*inv; o4.w = acc[4*i+3]*inv;
        ((float4*)yp)[i] = o4;
    }
}

// ---------------- router: softmax over 8 experts + top-2 ----------------
__global__ __launch_bounds__(256) void router_kernel(const float* __restrict__ rww,
                                                     float* __restrict__ out_rw) {
    int n = blockIdx.x;
    int lane = threadIdx.x & 31, w = threadIdx.x >> 5;
    const float* xr = g_xn2 + (long)n*C_;
    const float* wr = rww + (long)w*C_;
    float sum = 0.f;
    for (int kk = lane; kk < C_; kk += 32) sum = fmaf(xr[kk], wr[kk], sum);
    #pragma unroll
    for (int off = 16; off; off >>= 1) sum += __shfl_xor_sync(0xffffffffu, sum, off);
    __shared__ float lg[8];
    if (lane == 0) lg[w] = sum;
    __syncthreads();
    if (threadIdx.x == 0) {
        float mx = lg[0];
        #pragma unroll
        for (int e = 1; e < 8; e++) mx = lg[e] > mx ? lg[e] : mx;
        float ex[8], s = 0.f;
        #pragma unroll
        for (int e = 0; e < 8; e++) { ex[e] = __expf(lg[e] - mx); s += ex[e]; }
        float inv = 1.f / s;
        float rw[8];
        #pragma unroll
        for (int e = 0; e < 8; e++) { rw[e] = ex[e] * inv; out_rw[(long)n*E_ + e] = rw[e]; }
        int i0 = 0;
        #pragma unroll
        for (int e = 1; e < 8; e++) if (rw[e] > rw[i0]) i0 = e;
        int i1 = (i0 == 0) ? 1 : 0;
        #pragma unroll
        for (int e = 0; e < 8; e++) if (e != i0 && rw[e] > rw[i1]) i1 = e;
        float w0 = rw[i0], w1 = rw[i1];
        float d = w0 + w1 + 1e-10f;
        g_tke[2*n]   = i0; g_tke[2*n+1] = i1;
        g_tkw[2*n]   = w0 / d; g_tkw[2*n+1] = w1 / d;
    }
}

// ---------------- stable expert dispatch (single block) ----------------
__global__ __launch_bounds__(256) void route_kernel() {
    __shared__ int cnts[256][8];
    int tid = threadIdx.x;
    int c[8];
    #pragma unroll
    for (int e = 0; e < 8; e++) c[e] = 0;
    int base = tid * 32;
    for (int i = 0; i < 32; i++) c[g_tke[base + i]]++;
    #pragma unroll
    for (int e = 0; e < 8; e++) cnts[tid][e] = c[e];
    __syncthreads();
    if (tid < 8) {
        int run = 0;
        for (int t = 0; t < 256; t++) { int tmp = cnts[t][tid]; cnts[t][tid] = run; run += tmp; }
        g_me[tid] = run < CAP ? run : CAP;
    }
    __syncthreads();
    #pragma unroll
    for (int e = 0; e < 8; e++) c[e] = cnts[tid][e];
    for (int i = 0; i < 32; i++) {
        int gi = base + i;
        int e = g_tke[gi];
        int pos = c[e]++;
        if (pos < CAP) {
            int row = e * CAP + pos;
            g_rowsrc[row]   = gi >> 1;
            g_entryrow[gi]  = row;
        } else {
            g_entryrow[gi] = -1;
        }
    }
}

// ---------------- combine ----------------
__global__ __launch_bounds__(256) void combine_kernel(float* __restrict__ outx) {
    int n = blockIdx.x, tid = threadIdx.x;
    float4 r = ((const float4*)(g_x1 + (long)n*C_))[tid];
    #pragma unroll
    for (int s = 0; s < 2; s++) {
        int row = g_entryrow[n*2 + s];
        if (row >= 0) {
            float ww = g_tkw[n*2 + s];
            float4 bv = ((const float4*)(g_bo + (long)row*C_))[tid];
            r.x = fmaf(ww, bv.x, r.x); r.y = fmaf(ww, bv.y, r.y);
            r.z = fmaf(ww, bv.z, r.z); r.w = fmaf(ww, bv.w, r.w);
        }
    }
    ((float4*)(outx + (long)n*C_))[tid] = r;
}

// ---------------- host launcher ----------------
static inline void do_split(const float* src, void* hi, void* lo, long nelem) {
    int n2 = (int)(nelem >> 1);
    split_kernel<<<(n2 + 255)/256, 256>>>(src, (unsigned*)hi, (unsigned*)lo, n2);
}

extern "C" void kernel_launch(void* const* d_in, const int* in_sizes, int n_in,
                              void* d_out, int out_size) {
    const float* x    = (const float*)d_in[0];
    const float* ve   = (const float*)d_in[1];
    const float* cosb = (const float*)d_in[2];
    const float* sinb = (const float*)d_in[3];
    const float* cqw  = (const float*)d_in[4];
    const float* ckw  = (const float*)d_in[5];
    const float* cvw  = (const float*)d_in[6];
    const float* cpw  = (const float*)d_in[7];
    const float* gw   = (const float*)d_in[8];
    const float* rww  = (const float*)d_in[9];
    const float* fcw  = (const float*)d_in[10];
    const float* pjw  = (const float*)d_in[11];
    const int*   wptr = (const int*)d_in[12];
    float* out = (float*)d_out;

    float *xn, *qkv, *y, *x1, *xn2, *bo;
    int *rowsrc, *me;
    cudaGetSymbolAddress((void**)&xn,  g_xn);
    cudaGetSymbolAddress((void**)&qkv, g_qkv);
    cudaGetSymbolAddress((void**)&y,   g_y);
    cudaGetSymbolAddress((void**)&x1,  g_x1);
    cudaGetSymbolAddress((void**)&xn2, g_xn2);
    cudaGetSymbolAddress((void**)&bo,  g_bo);
    cudaGetSymbolAddress((void**)&rowsrc, g_rowsrc);
    cudaGetSymbolAddress((void**)&me,     g_me);

    void *xnh,*xnl, *yh,*yl, *xn2h,*xn2l;
    void *wqkvh,*wqkvl, *wph,*wpl, *wfh,*wfl, *wjh,*wjl, *hh,*hl;
    cudaGetSymbolAddress(&xnh, s_xn_h);   cudaGetSymbolAddress(&xnl, s_xn_l);
    cudaGetSymbolAddress(&yh,  s_y_h);    cudaGetSymbolAddress(&yl,  s_y_l);
    cudaGetSymbolAddress(&xn2h,s_xn2_h);  cudaGetSymbolAddress(&xn2l,s_xn2_l);
    cudaGetSymbolAddress(&wqkvh, w_qkv_h); cudaGetSymbolAddress(&wqkvl, w_qkv_l);
    cudaGetSymbolAddress(&wph, w_p_h);    cudaGetSymbolAddress(&wpl, w_p_l);
    cudaGetSymbolAddress(&wfh, w_fc_h);   cudaGetSymbolAddress(&wfl, w_fc_l);
    cudaGetSymbolAddress(&wjh, w_pj_h);   cudaGetSymbolAddress(&wjl, w_pj_l);
    cudaGetSymbolAddress(&hh,  s_h_h);    cudaGetSymbolAddress(&hl,  s_h_l);

    const int SMEM = 3*49152;  // 144KB
    cudaFuncSetAttribute(gemm_bf, cudaFuncAttributeMaxDynamicSharedMemorySize, SMEM);

    typedef const ushort_t* cus;

    // weight splits: q rows [0,1024), k rows [1024,1536), v rows [1536,2048)
    do_split(cqw, wqkvh, wqkvl, (long)NH*HD*C_);
    do_split(ckw, (ushort_t*)wqkvh + (long)1024*C_, (ushort_t*)wqkvl + (long)1024*C_,
             (long)NKV*HD*C_);
    do_split(cvw, (ushort_t*)wqkvh + (long)1536*C_, (ushort_t*)wqkvl + (long)1536*C_,
             (long)NKV*HD*C_);
    do_split(cpw, wph, wpl, (long)C_*C_);
    do_split(fcw, wfh, wfl, (long)E_*H_*C_);
    do_split(pjw, wjh, wjl, (long)E_*C_*H_);

    // 1) xn = rms(x); split
    rms_kernel<<<NTOK, 256>>>(x, xn);
    do_split(xn, xnh, xnl, (long)NTOK*C_);

    // 2) fused q/k/v projection (N = 2048)
    gemm_bf<<<dim3(QS/256, NTOK/128, 1), 256, SMEM>>>(
        (cus)xnh, (cus)xnl, 0, (cus)wqkvh, (cus)wqkvl, 0,
        qkv, nullptr, nullptr, 0, nullptr, NTOK, QS, C_, nullptr, nullptr, 0);

    // 3) gate + v update + rope + q/k rms
    gate_rope_kernel<<<NTOK, 256>>>(ve, cosb, sinb, gw);
    // 4) attention
    attn_kernel<<<dim3(T_/128, NH, B_), 128>>>(wptr);
    // 5) x1 = x + y @ c_proj^T
    do_split(y, yh, yl, (long)NTOK*C_);
    gemm_bf<<<dim3(C_/256, NTOK/128, 1), 256, SMEM>>>(
        (cus)yh, (cus)yl, 0, (cus)wph, (cus)wpl, 0,
        x1, nullptr, nullptr, 0, x, NTOK, C_, C_, nullptr, nullptr, 1);
    // 6) xn2 = rms(x1); split
    rms_kernel<<<NTOK, 256>>>(x1, xn2);
    do_split(xn2, xn2h, xn2l, (long)NTOK*C_);
    // 7) router softmax + top-2 (fp32 exact; writes rw output region)
    router_kernel<<<NTOK, 256>>>(rww, out + (long)NTOK * C_);
    // 8) stable dispatch
    route_kernel<<<1, 256>>>();
    // 9) h = relu(xn2[gather] @ fc_w[e]^T)^2  -> split bf16 out
    gemm_bf<<<dim3(H_/256, CAP/128, E_), 256, SMEM>>>(
        (cus)xn2h, (cus)xn2l, 0, (cus)wfh, (cus)wfl, (long)H_*C_,
        nullptr, (unsigned*)hh, (unsigned*)hl, (long)CAP*H_, nullptr,
        CAP, H_, C_, rowsrc, me, 2);
    // 10) bo = h @ proj_w[e]^T
    gemm_bf<<<dim3(C_/256, CAP/128, E_), 256, SMEM>>>(
        (cus)hh, (cus)hl, (long)CAP*H_, (cus)wjh, (cus)wjl, (long)C_*H_,
        bo, nullptr, nullptr, (long)CAP*C_, nullptr,
        CAP, C_, H_, nullptr, me, 0);
    // 11) final combine -> x output region
    combine_kernel<<<NTOK, 256>>>(out);
}

// round 17
// speedup vs baseline: 2.4003x; 1.4385x over previous
#include <cuda_runtime.h>

// ---------------- problem constants ----------------
#define B_    2
#define T_    2048
#define C_    1024
#define NH    16
#define NKV   8
#define HD    64
#define E_    8
#define H_    2048
#define NTOK  (B_*T_)        // 4096
#define TOPK  2
#define CAP   2048           // 2*NTOK*TOPK/E_
#define EPSF  1.1920928955078125e-07f
#define QS    2048           // fused qkv row stride (1024 q + 512 k + 512 v)

typedef unsigned short ushort_t;

// ---------------- scratch (device globals; no runtime alloc) ----------------
__device__ float g_xn [NTOK*C_];
__device__ float g_qkv[NTOK*QS];
__device__ float g_y  [NTOK*C_];
__device__ float g_x1 [NTOK*C_];
__device__ float g_xn2[NTOK*C_];
__device__ float g_bo [E_*CAP*C_];
__device__ int   g_tke[NTOK*TOPK];
__device__ float g_tkw[NTOK*TOPK];
__device__ int   g_rowsrc[E_*CAP];
__device__ int   g_entryrow[NTOK*TOPK];
__device__ int   g_me[E_];

// bf16 hi/lo split buffers (GEMM)
__device__ ushort_t s_xn_h [NTOK*C_],      s_xn_l [NTOK*C_];
__device__ ushort_t s_y_h  [NTOK*C_],      s_y_l  [NTOK*C_];
__device__ ushort_t s_xn2_h[NTOK*C_],      s_xn2_l[NTOK*C_];
__device__ ushort_t w_qkv_h[QS*C_],        w_qkv_l[QS*C_];
__device__ ushort_t w_p_h [C_*C_],         w_p_l [C_*C_];
__device__ ushort_t w_fc_h[E_*H_*C_],      w_fc_l[E_*H_*C_];
__device__ ushort_t w_pj_h[E_*C_*H_],      w_pj_l[E_*C_*H_];
__device__ ushort_t s_h_h [E_*CAP*H_],     s_h_l [E_*CAP*H_];

// attention bf16 hi/lo buffers
__device__ ushort_t a_q_h [B_*NH*T_*HD],   a_q_l [B_*NH*T_*HD];
__device__ ushort_t a_k_h [B_*NKV*T_*HD],  a_k_l [B_*NKV*T_*HD];
__device__ ushort_t a_vt_h[B_*NKV*HD*T_],  a_vt_l[B_*NKV*HD*T_];

// ---------------- helpers ----------------
__device__ __forceinline__ void split2(float f0, float f1, unsigned &hi, unsigned &lo) {
    unsigned h;
    asm("cvt.rn.bf16x2.f32 %0, %1, %2;" : "=r"(h) : "f"(f1), "f"(f0));
    float h0 = __uint_as_float(h << 16);
    float h1 = __uint_as_float(h & 0xffff0000u);
    float r0 = f0 - h0;
    float r1 = f1 - h1;
    unsigned l;
    asm("cvt.rn.bf16x2.f32 %0, %1, %2;" : "=r"(l) : "f"(r1), "f"(r0));
    hi = h; lo = l;
}
__device__ __forceinline__ void mma_bf16(float* c, const unsigned* a, const unsigned* b) {
    asm volatile(
        "mma.sync.aligned.m16n8k16.row.col.f32.bf16.bf16.f32 "
        "{%0,%1,%2,%3},{%4,%5,%6,%7},{%8,%9},{%0,%1,%2,%3};"
        : "+f"(c[0]), "+f"(c[1]), "+f"(c[2]), "+f"(c[3])
        : "r"(a[0]), "r"(a[1]), "r"(a[2]), "r"(a[3]), "r"(b[0]), "r"(b[1]));
}
__device__ __forceinline__ void ldsm4(unsigned &r0, unsigned &r1, unsigned &r2, unsigned &r3,
                                      unsigned addr) {
    asm volatile("ldmatrix.sync.aligned.m8n8.x4.shared.b16 {%0,%1,%2,%3}, [%4];"
                 : "=r"(r0), "=r"(r1), "=r"(r2), "=r"(r3) : "r"(addr));
}
#define CPA16(dst, src) asm volatile("cp.async.cg.shared.global [%0], [%1], 16;" :: "r"(dst), "l"(src))

// ---------------- split: f32 -> bf16 hi/lo ----------------
__global__ __launch_bounds__(256) void split_kernel(const float* __restrict__ in,
                                                    unsigned* __restrict__ hi,
                                                    unsigned* __restrict__ lo, int n2) {
    int i = blockIdx.x*256 + threadIdx.x;
    if (i < n2) {
        float2 f = ((const float2*)in)[i];
        unsigned h, l;
        split2(f.x, f.y, h, l);
        hi[i] = h; lo[i] = l;
    }
}

// ---------------- RMS norm ----------------
__global__ __launch_bounds__(256) void rms_kernel(const float* __restrict__ x,
                                                  float* __restrict__ o) {
    int row = blockIdx.x;
    const float4* xr = (const float4*)(x + (long)row*C_);
    float4 v = xr[threadIdx.x];
    float ss = v.x*v.x + v.y*v.y + v.z*v.z + v.w*v.w;
    #pragma unroll
    for (int off = 16; off; off >>= 1) ss += __shfl_xor_sync(0xffffffffu, ss, off);
    __shared__ float sred[8];
    if ((threadIdx.x & 31) == 0) sred[threadIdx.x >> 5] = ss;
    __syncthreads();
    if (threadIdx.x == 0) {
        float t = 0.f;
        #pragma unroll
        for (int i = 0; i < 8; i++) t += sred[i];
        sred[0] = rsqrtf(t / (float)C_ + EPSF);
    }
    __syncthreads();
    float s = sred[0];
    v.x *= s; v.y *= s; v.z *= s; v.w *= s;
    ((float4*)(o + (long)row*C_))[threadIdx.x] = v;
}

// ---------------- bf16 hi/lo split-precision tensor GEMM ----------------
// (identical to R16 best)
__global__ __launch_bounds__(256, 1) void gemm_bf(
    const ushort_t* __restrict__ Ah, const ushort_t* __restrict__ Al, long sA,
    const ushort_t* __restrict__ Bh, const ushort_t* __restrict__ Bl, long sB,
    float* __restrict__ Cf, unsigned* __restrict__ Chi, unsigned* __restrict__ Clo, long sC,
    const float* __restrict__ Res,
    int M, int N, int K,
    const int* __restrict__ rowsrc, const int* __restrict__ mcounts, int epi)
{
    constexpr int BK = 32;
    constexpr unsigned STG = 49152u;
    int e  = blockIdx.z;
    int Mz = mcounts ? mcounts[e] : M;
    int m0 = blockIdx.y * 128;
    if (m0 >= Mz) return;
    int n0 = blockIdx.x * 256;

    const ushort_t* Ahb = Ah + (long)e * sA;
    const ushort_t* Alb = Al + (long)e * sA;
    const ushort_t* Bhb = Bh + (long)e * sB;
    const ushort_t* Blb = Bl + (long)e * sB;

    extern __shared__ ushort_t sm[];
    unsigned sbase = (unsigned)__cvta_generic_to_shared(sm);

    int tid = threadIdx.x;
    int lr = tid >> 2, lc = tid & 3;

    long aoff[2]; int adst[2];
    #pragma unroll
    for (int t = 0; t < 2; t++) {
        int r  = lr + 64*t;
        int gm = m0 + r; if (gm >= Mz) gm = Mz - 1;
        int grow = rowsrc ? rowsrc[e*CAP + gm] : gm;
        aoff[t] = (long)grow*K + lc*8;
        adst[t] = r*64 + ((lc ^ ((r>>1)&3)) << 4);
    }
    long boff[4]; int bdst[4];
    #pragma unroll
    for (int t = 0; t < 4; t++) {
        int r = lr + 64*t;
        boff[t] = (long)(n0 + r)*K + lc*8;
        bdst[t] = r*64 + ((lc ^ ((r>>1)&3)) << 4);
    }

    auto load_tile = [&](int stage, int k0) {
        unsigned sb = sbase + stage*STG;
        #pragma unroll
        for (int t = 0; t < 2; t++) {
            CPA16(sb + adst[t],          Ahb + aoff[t] + k0);
            CPA16(sb + 8192u + adst[t],  Alb + aoff[t] + k0);
        }
        #pragma unroll
        for (int t = 0; t < 4; t++) {
            CPA16(sb + 16384u + bdst[t], Bhb + boff[t] + k0);
            CPA16(sb + 32768u + bdst[t], Blb + boff[t] + k0);
        }
        asm volatile("cp.async.commit_group;");
    };

    int wid = tid >> 5, lane = tid & 31;
    int wm = wid >> 2, wn = wid & 3;
    int g = lane >> 2, tig = lane & 3;

    int rA[4], rAx[4];
    #pragma unroll
    for (int i = 0; i < 4; i++) { rA[i] = wm*64 + i*16 + (lane & 15); rAx[i] = (rA[i]>>1)&3; }
    int chA = lane >> 4;
    int rB[4], rBx[4];
    #pragma unroll
    for (int jp = 0; jp < 4; jp++) {
        rB[jp]  = wn*64 + jp*16 + 8*(lane>>4) + (lane & 7);
        rBx[jp] = (rB[jp]>>1)&3;
    }
    int chB = (lane >> 3) & 1;

    float acc[4][8][4];
    #pragma unroll
    for (int i = 0; i < 4; i++)
        #pragma unroll
        for (int j = 0; j < 8; j++)
            #pragma unroll
            for (int q = 0; q < 4; q++) acc[i][j][q] = 0.f;

    auto compute = [&](int stage) {
        unsigned sb = sbase + stage*STG;
        #pragma unroll
        for (int kc = 0; kc < 2; kc++) {
            unsigned bh[8][2], bl[8][2];
            #pragma unroll
            for (int jp = 0; jp < 4; jp++) {
                unsigned addr = sb + 16384u + (unsigned)(rB[jp]*64 + (((kc*2 + chB) ^ rBx[jp]) << 4));
                ldsm4(bh[2*jp][0], bh[2*jp][1], bh[2*jp+1][0], bh[2*jp+1][1], addr);
                ldsm4(bl[2*jp][0], bl[2*jp][1], bl[2*jp+1][0], bl[2*jp+1][1], addr + 16384u);
            }
            #pragma unroll
            for (int i = 0; i < 4; i++) {
                unsigned addrA = sb + (unsigned)(rA[i]*64 + (((kc*2 + chA) ^ rAx[i]) << 4));
                unsigned ah[4], al[4];
                ldsm4(ah[0], ah[1], ah[2], ah[3], addrA);
                ldsm4(al[0], al[1], al[2], al[3], addrA + 8192u);
                #pragma unroll
                for (int j = 0; j < 8; j++) {
                    mma_bf16(acc[i][j], ah, bh[j]);
                    mma_bf16(acc[i][j], ah, bl[j]);
                    mma_bf16(acc[i][j], al, bh[j]);
                }
            }
        }
    };

    int KT = K / BK;
    load_tile(0, 0);
    load_tile(1, BK);
    for (int kt = 0; kt < KT; kt++) {
        if (kt + 2 < KT) {
            load_tile((kt + 2) % 3, (kt + 2)*BK);
            asm volatile("cp.async.wait_group 2;");
        } else {
            asm volatile("cp.async.wait_group 0;");
        }
        __syncthreads();
        compute(kt % 3);
        __syncthreads();
    }

    #pragma unroll
    for (int i = 0; i < 4; i++) {
        int rm0 = m0 + wm*64 + i*16 + g;
        #pragma unroll
        for (int half = 0; half < 2; half++) {
            int rm = rm0 + half*8;
            if (rm < Mz) {
                #pragma unroll
                for (int j = 0; j < 8; j++) {
                    int col = n0 + wn*64 + j*8 + tig*2;
                    float v0 = acc[i][j][half*2 + 0];
                    float v1 = acc[i][j][half*2 + 1];
                    if (epi == 1) {
                        float2 rr = *(const float2*)&Res[(long)rm*N + col];
                        v0 += rr.x; v1 += rr.y;
                        *(float2*)&Cf[(long)e*sC + (long)rm*N + col] = make_float2(v0, v1);
                    } else if (epi == 2) {
                        v0 = fmaxf(v0, 0.f); v0 *= v0;
                        v1 = fmaxf(v1, 0.f); v1 *= v1;
                        unsigned h, l;
                        split2(v0, v1, h, l);
                        long idx = ((long)e*sC + (long)rm*N + col) >> 1;
                        Chi[idx] = h; Clo[idx] = l;
                    } else {
                        *(float2*)&Cf[(long)e*sC + (long)rm*N + col] = make_float2(v0, v1);
                    }
                }
            }
        }
    }
}

// ---------------- gate + v-update + RoPE + q/k RMS (fused qkv layout) ----------------
__global__ __launch_bounds__(256) void gate_rope_kernel(
    const float* __restrict__ ve, const float* __restrict__ cosb,
    const float* __restrict__ sinb, const float* __restrict__ gw)
{
    int n = blockIdx.x;
    int tid = threadIdx.x, lane = tid & 31, w = tid >> 5;
    __shared__ float gs[8];
    float gsum = g_xn[(long)n*C_ + lane] * gw[w*32 + lane];
    #pragma unroll
    for (int off = 16; off; off >>= 1) gsum += __shfl_xor_sync(0xffffffffu, gsum, off);
    if (lane == 0) gs[w] = 2.f / (1.f + __expf(-gsum));
    __syncthreads();
    for (int idx = tid; idx < NKV*HD; idx += 256) {
        int kvh = idx >> 6;
        g_qkv[(long)n*QS + 1536 + idx] += gs[kvh] * ve[(long)n*(NKV*HD) + idx];
    }
    int ts = n & (T_ - 1);
    float c = cosb[ts*32 + lane], s = sinb[ts*32 + lane];
    #pragma unroll
    for (int hh = 0; hh < 3; hh++) {
        float* p;
        if (hh == 0)      p = g_qkv + (long)n*QS + w*HD;
        else if (hh == 1) p = g_qkv + (long)n*QS + (w+8)*HD;
        else              p = g_qkv + (long)n*QS + 1024 + w*HD;
        float x1 = p[lane], x2 = p[lane + 32];
        float o1 = x1*c + x2*s;
        float o2 = x2*c - x1*s;
        float ss = o1*o1 + o2*o2;
        #pragma unroll
        for (int off = 16; off; off >>= 1) ss += __shfl_xor_sync(0xffffffffu, ss, off);
        ss = __shfl_sync(0xffffffffu, ss, 0);
        float r = rsqrtf(ss / (float)HD + EPSF);
        p[lane]      = o1 * r;
        p[lane + 32] = o2 * r;
    }
}

// ---------------- attention prep: Q (scaled) and K -> bf16 hi/lo ----------------
__global__ __launch_bounds__(256) void q_prep_kernel() {
    int idx = blockIdx.x*256 + threadIdx.x;      // [B*T][NH][32]
    int d2 = idx & 31;
    int rem = idx >> 5;
    int hh = rem & 15;
    int bt = rem >> 4;
    float2 f = ((const float2*)g_qkv)[(long)bt*(QS/2) + hh*32 + d2];
    unsigned h, l;
    split2(f.x * 0.125f, f.y * 0.125f, h, l);
    long w = (((long)(bt >> 11)*NH + hh)*T_ + (bt & (T_-1)))*32 + d2;
    ((unsigned*)a_q_h)[w] = h;
    ((unsigned*)a_q_l)[w] = l;
}
__global__ __launch_bounds__(256) void k_prep_kernel() {
    int idx = blockIdx.x*256 + threadIdx.x;      // [B*T][NKV][32]
    int d2 = idx & 31;
    int rem = idx >> 5;
    int kv = rem & 7;
    int bt = rem >> 3;
    float2 f = ((const float2*)g_qkv)[(long)bt*(QS/2) + 512 + kv*32 + d2];
    unsigned h, l;
    split2(f.x, f.y, h, l);
    long w = (((long)(bt >> 11)*NKV + kv)*T_ + (bt & (T_-1)))*32 + d2;
    ((unsigned*)a_k_h)[w] = h;
    ((unsigned*)a_k_l)[w] = l;
}
// V transpose: [t][d] -> [d][t] bf16 hi/lo
__global__ __launch_bounds__(256) void vt_prep_kernel() {
    __shared__ float ts[64][65];
    int tt = blockIdx.x*64, kv = blockIdx.y, b = blockIdx.z;
    int tid = threadIdx.x;
    int row = tid >> 2, q4 = tid & 3;
    #pragma unroll
    for (int i = 0; i < 4; i++) {
        int c4 = q4*4 + i;
        float4 v = *(const float4*)&g_qkv[((long)(b*T_ + tt + row))*QS + 1536 + kv*64 + c4*4];
        ts[row][c4*4+0] = v.x; ts[row][c4*4+1] = v.y;
        ts[row][c4*4+2] = v.z; ts[row][c4*4+3] = v.w;
    }
    __syncthreads();
    int d = tid >> 2, seg = tid & 3;
    long obase = ((((long)(b*NKV + kv))*HD + d)*T_ + tt) >> 1;
    #pragma unroll
    for (int i = 0; i < 8; i++) {
        int tp = i*4 + seg;
        unsigned h, l;
        split2(ts[2*tp][d], ts[2*tp+1][d], h, l);
        ((unsigned*)a_vt_h)[obase + tp] = h;
        ((unsigned*)a_vt_l)[obase + tp] = l;
    }
}

// ---------------- tensor-core flash attention, fixed max = 8 ----------------
// grid (T/64, NH, B); 128 threads (4 warps, warp = 16 q rows)
__global__ __launch_bounds__(128) void attn_tc(const int* __restrict__ wptr) {
    int W = wptr[0];
    int b = blockIdx.z, h = blockIdx.y, q0 = blockIdx.x*64, kvh = h >> 1;
    extern __shared__ ushort_t smA[];
    unsigned sb = (unsigned)__cvta_generic_to_shared(smA);
    // Q hi @0, Q lo @8192; stage st @16384+st*32768: Khi 0 | Klo 8192 | VThi 16384 | VTlo 24576
    int tid = threadIdx.x;
    int row = tid >> 1, half = tid & 1;

    // Q tile load (no commit; joins stage-0 group)
    {
        long src = ((long)(b*NH + h)*T_ + q0 + row)*HD + half*32;
        #pragma unroll
        for (int c = 0; c < 4; c++) {
            int cc = half*4 + c;
            unsigned dst = (unsigned)(row*128 + ((cc ^ (row & 7)) << 4));
            CPA16(sb + dst,         a_q_h + src + c*8);
            CPA16(sb + 8192u + dst, a_q_l + src + c*8);
        }
    }
    int jlo = q0 - W; if (jlo < 0) jlo = 0; jlo &= ~63;
    int nt = (q0 - jlo)/64 + 1;

    auto load_stage = [&](int st, int j0) {
        unsigned base = sb + 16384u + (unsigned)st*32768u;
        long ksrc = ((long)(b*NKV + kvh)*T_ + j0 + row)*HD + half*32;
        long vsrc = ((long)(b*NKV + kvh)*HD + row)*T_ + j0 + half*32;
        #pragma unroll
        for (int c = 0; c < 4; c++) {
            int cc = half*4 + c;
            unsigned dst = (unsigned)(row*128 + ((cc ^ (row & 7)) << 4));
            CPA16(base + dst,          a_k_h  + ksrc + c*8);
            CPA16(base + 8192u + dst,  a_k_l  + ksrc + c*8);
            CPA16(base + 16384u + dst, a_vt_h + vsrc + c*8);
            CPA16(base + 24576u + dst, a_vt_l + vsrc + c*8);
        }
        asm volatile("cp.async.commit_group;");
    };

    load_stage(0, jlo);

    int lane = tid & 31, wid = tid >> 5;
    int g = lane >> 2, tig = lane & 3;
    int rA = wid*16 + (lane & 15); int rAx = rA & 7; int chA = lane >> 4;
    int rB[4], rBx[4];
    #pragma unroll
    for (int jp = 0; jp < 4; jp++) {
        rB[jp]  = jp*16 + 8*(lane >> 4) + (lane & 7);
        rBx[jp] = rB[jp] & 7;
    }
    int chB = (lane >> 3) & 1;

    float o[8][4];
    #pragma unroll
    for (int j = 0; j < 8; j++)
        #pragma unroll
        for (int q = 0; q < 4; q++) o[j][q] = 0.f;
    float li[2] = {0.f, 0.f};
    int qi0 = q0 + wid*16 + g;

    for (int it = 0; it < nt; it++) {
        int j0 = jlo + it*64;
        if (it + 1 < nt) {
            load_stage((it + 1) & 1, j0 + 64);
            asm volatile("cp.async.wait_group 1;");
        } else {
            asm volatile("cp.async.wait_group 0;");
        }
        __syncthreads();
        unsigned base = sb + 16384u + (unsigned)(it & 1)*32768u;

        // ---- S = Q K^T ----
        float s[8][4];
        #pragma unroll
        for (int j = 0; j < 8; j++)
            #pragma unroll
            for (int q = 0; q < 4; q++) s[j][q] = 0.f;
        #pragma unroll
        for (int kk = 0; kk < 4; kk++) {
            unsigned qa = sb + (unsigned)(rA*128 + (((2*kk + chA) ^ rAx) << 4));
            unsigned ah[4], al[4];
            ldsm4(ah[0], ah[1], ah[2], ah[3], qa);
            ldsm4(al[0], al[1], al[2], al[3], qa + 8192u);
            unsigned bh[8][2], bl[8][2];
            #pragma unroll
            for (int jp = 0; jp < 4; jp++) {
                unsigned ka = base + (unsigned)(rB[jp]*128 + (((2*kk + chB) ^ rBx[jp]) << 4));
                ldsm4(bh[2*jp][0], bh[2*jp][1], bh[2*jp+1][0], bh[2*jp+1][1], ka);
                ldsm4(bl[2*jp][0], bl[2*jp][1], bl[2*jp+1][0], bl[2*jp+1][1], ka + 8192u);
            }
            #pragma unroll
            for (int jt = 0; jt < 8; jt++) {
                mma_bf16(s[jt], ah, bh[jt]);
                mma_bf16(s[jt], ah, bl[jt]);
                mma_bf16(s[jt], al, bh[jt]);
            }
        }

        // ---- mask + exp (fixed max 8) ----
        #pragma unroll
        for (int jt = 0; jt < 8; jt++) {
            #pragma unroll
            for (int eI = 0; eI < 4; eI++) {
                int j  = j0 + jt*8 + tig*2 + (eI & 1);
                int qi = qi0 + (eI >> 1)*8;
                float p = 0.f;
                if (j <= qi && qi - j <= W) p = __expf(s[jt][eI] - 8.f);
                s[jt][eI] = p;
                li[eI >> 1] += p;
            }
        }

        // ---- O += P V ----
        unsigned vbase = base + 16384u;
        #pragma unroll
        for (int kk = 0; kk < 4; kk++) {
            unsigned ph[4], pl[4];
            split2(s[2*kk][0],   s[2*kk][1],   ph[0], pl[0]);
            split2(s[2*kk][2],   s[2*kk][3],   ph[1], pl[1]);
            split2(s[2*kk+1][0], s[2*kk+1][1], ph[2], pl[2]);
            split2(s[2*kk+1][2], s[2*kk+1][3], ph[3], pl[3]);
            unsigned vh[8][2], vl[8][2];
            #pragma unroll
            for (int jp = 0; jp < 4; jp++) {
                unsigned va = vbase + (unsigned)(rB[jp]*128 + (((2*kk + chB) ^ rBx[jp]) << 4));
                ldsm4(vh[2*jp][0], vh[2*jp][1], vh[2*jp+1][0], vh[2*jp+1][1], va);
                ldsm4(vl[2*jp][0], vl[2*jp][1], vl[2*jp+1][0], vl[2*jp+1][1], va + 8192u);
            }
            #pragma unroll
            for (int jt = 0; jt < 8; jt++) {
                mma_bf16(o[jt], ph, vh[jt]);
                mma_bf16(o[jt], ph, vl[jt]);
                mma_bf16(o[jt], pl, vh[jt]);
            }
        }
        __syncthreads();
    }

    // ---- finalize: 1/sum over quad, write ----
    float inv[2];
    #pragma unroll
    for (int q = 0; q < 2; q++) {
        float t = li[q];
        t += __shfl_xor_sync(0xffffffffu, t, 1);
        t += __shfl_xor_sync(0xffffffffu, t, 2);
        inv[q] = 1.f / t;
    }
    #pragma unroll
    for (int q = 0; q < 2; q++) {
        int qi = qi0 + q*8;
        float* yp = g_y + ((long)(b*T_ + qi))*C_ + h*HD;
        #pragma unroll
        for (int jt = 0; jt < 8; jt++) {
            float2 w2 = make_float2(o[jt][2*q]*inv[q], o[jt][2*q+1]*inv[q]);
            *(float2*)&yp[jt*8 + tig*2] = w2;
        }
    }
}

// ---------------- router: softmax over 8 experts + top-2 ----------------
__global__ __launch_bounds__(256) void router_kernel(const float* __restrict__ rww,
                                                     float* __restrict__ out_rw) {
    int n = blockIdx.x;
    int lane = threadIdx.x & 31, w = threadIdx.x >> 5;
    const float* xr = g_xn2 + (long)n*C_;
    const float* wr = rww + (long)w*C_;
    float sum = 0.f;
    for (int kk = lane; kk < C_; kk += 32) sum = fmaf(xr[kk], wr[kk], sum);
    #pragma unroll
    for (int off = 16; off; off >>= 1) sum += __shfl_xor_sync(0xffffffffu, sum, off);
    __shared__ float lg[8];
    if (lane == 0) lg[w] = sum;
    __syncthreads();
    if (threadIdx.x == 0) {
        float mx = lg[0];
        #pragma unroll
        for (int e = 1; e < 8; e++) mx = lg[e] > mx ? lg[e] : mx;
        float ex[8], s = 0.f;
        #pragma unroll
        for (int e = 0; e < 8; e++) { ex[e] = __expf(lg[e] - mx); s += ex[e]; }
        float inv = 1.f / s;
        float rw[8];
        #pragma unroll
        for (int e = 0; e < 8; e++) { rw[e] = ex[e] * inv; out_rw[(long)n*E_ + e] = rw[e]; }
        int i0 = 0;
        #pragma unroll
        for (int e = 1; e < 8; e++) if (rw[e] > rw[i0]) i0 = e;
        int i1 = (i0 == 0) ? 1 : 0;
        #pragma unroll
        for (int e = 0; e < 8; e++) if (e != i0 && rw[e] > rw[i1]) i1 = e;
        float w0 = rw[i0], w1 = rw[i1];
        float d = w0 + w1 + 1e-10f;
        g_tke[2*n]   = i0; g_tke[2*n+1] = i1;
        g_tkw[2*n]   = w0 / d; g_tkw[2*n+1] = w1 / d;
    }
}

// ---------------- stable expert dispatch (single block) ----------------
__global__ __launch_bounds__(256) void route_kernel() {
    __shared__ int cnts[256][8];
    int tid = threadIdx.x;
    int c[8];
    #pragma unroll
    for (int e = 0; e < 8; e++) c[e] = 0;
    int base = tid * 32;
    for (int i = 0; i < 32; i++) c[g_tke[base + i]]++;
    #pragma unroll
    for (int e = 0; e < 8; e++) cnts[tid][e] = c[e];
    __syncthreads();
    if (tid < 8) {
        int run = 0;
        for (int t = 0; t < 256; t++) { int tmp = cnts[t][tid]; cnts[t][tid] = run; run += tmp; }
        g_me[tid] = run < CAP ? run : CAP;
    }
    __syncthreads();
    #pragma unroll
    for (int e = 0; e < 8; e++) c[e] = cnts[tid][e];
    for (int i = 0; i < 32; i++) {
        int gi = base + i;
        int e = g_tke[gi];
        int pos = c[e]++;
        if (pos < CAP) {
            int row = e * CAP + pos;
            g_rowsrc[row]   = gi >> 1;
            g_entryrow[gi]  = row;
        } else {
            g_entryrow[gi] = -1;
        }
    }
}

// ---------------- combine ----------------
__global__ __launch_bounds__(256) void combine_kernel(float* __restrict__ outx) {
    int n = blockIdx.x, tid = threadIdx.x;
    float4 r = ((const float4*)(g_x1 + (long)n*C_))[tid];
    #pragma unroll
    for (int s = 0; s < 2; s++) {
        int row = g_entryrow[n*2 + s];
        if (row >= 0) {
            float ww = g_tkw[n*2 + s];
            float4 bv = ((const float4*)(g_bo + (long)row*C_))[tid];
            r.x = fmaf(ww, bv.x, r.x); r.y = fmaf(ww, bv.y, r.y);
            r.z = fmaf(ww, bv.z, r.z); r.w = fmaf(ww, bv.w, r.w);
        }
    }
    ((float4*)(outx + (long)n*C_))[tid] = r;
}

// ---------------- host launcher ----------------
static inline void do_split(const float* src, void* hi, void* lo, long nelem) {
    int n2 = (int)(nelem >> 1);
    split_kernel<<<(n2 + 255)/256, 256>>>(src, (unsigned*)hi, (unsigned*)lo, n2);
}

extern "C" void kernel_launch(void* const* d_in, const int* in_sizes, int n_in,
                              void* d_out, int out_size) {
    const float* x    = (const float*)d_in[0];
    const float* ve   = (const float*)d_in[1];
    const float* cosb = (const float*)d_in[2];
    const float* sinb = (const float*)d_in[3];
    const float* cqw  = (const float*)d_in[4];
    const float* ckw  = (const float*)d_in[5];
    const float* cvw  = (const float*)d_in[6];
    const float* cpw  = (const float*)d_in[7];
    const float* gw   = (const float*)d_in[8];
    const float* rww  = (const float*)d_in[9];
    const float* fcw  = (const float*)d_in[10];
    const float* pjw  = (const float*)d_in[11];
    const int*   wptr = (const int*)d_in[12];
    float* out = (float*)d_out;

    float *xn, *qkv, *y, *x1, *xn2, *bo;
    int *rowsrc, *me;
    cudaGetSymbolAddress((void**)&xn,  g_xn);
    cudaGetSymbolAddress((void**)&qkv, g_qkv);
    cudaGetSymbolAddress((void**)&y,   g_y);
    cudaGetSymbolAddress((void**)&x1,  g_x1);
    cudaGetSymbolAddress((void**)&xn2, g_xn2);
    cudaGetSymbolAddress((void**)&bo,  g_bo);
    cudaGetSymbolAddress((void**)&rowsrc, g_rowsrc);
    cudaGetSymbolAddress((void**)&me,     g_me);

    void *xnh,*xnl, *yh,*yl, *xn2h,*xn2l;
    void *wqkvh,*wqkvl, *wph,*wpl, *wfh,*wfl, *wjh,*wjl, *hh,*hl;
    cudaGetSymbolAddress(&xnh, s_xn_h);   cudaGetSymbolAddress(&xnl, s_xn_l);
    cudaGetSymbolAddress(&yh,  s_y_h);    cudaGetSymbolAddress(&yl,  s_y_l);
    cudaGetSymbolAddress(&xn2h,s_xn2_h);  cudaGetSymbolAddress(&xn2l,s_xn2_l);
    cudaGetSymbolAddress(&wqkvh, w_qkv_h); cudaGetSymbolAddress(&wqkvl, w_qkv_l);
    cudaGetSymbolAddress(&wph, w_p_h);    cudaGetSymbolAddress(&wpl, w_p_l);
    cudaGetSymbolAddress(&wfh, w_fc_h);   cudaGetSymbolAddress(&wfl, w_fc_l);
    cudaGetSymbolAddress(&wjh, w_pj_h);   cudaGetSymbolAddress(&wjl, w_pj_l);
    cudaGetSymbolAddress(&hh,  s_h_h);    cudaGetSymbolAddress(&hl,  s_h_l);

    const int SMEM = 3*49152;          // gemm: 144KB
    const int ASMEM = 16384 + 2*32768; // attn: 80KB
    cudaFuncSetAttribute(gemm_bf, cudaFuncAttributeMaxDynamicSharedMemorySize, SMEM);
    cudaFuncSetAttribute(attn_tc, cudaFuncAttributeMaxDynamicSharedMemorySize, ASMEM);

    typedef const ushort_t* cus;

    // weight splits: q rows [0,1024), k rows [1024,1536), v rows [1536,2048)
    do_split(cqw, wqkvh, wqkvl, (long)NH*HD*C_);
    do_split(ckw, (ushort_t*)wqkvh + (long)1024*C_, (ushort_t*)wqkvl + (long)1024*C_,
             (long)NKV*HD*C_);
    do_split(cvw, (ushort_t*)wqkvh + (long)1536*C_, (ushort_t*)wqkvl + (long)1536*C_,
             (long)NKV*HD*C_);
    do_split(cpw, wph, wpl, (long)C_*C_);
    do_split(fcw, wfh, wfl, (long)E_*H_*C_);
    do_split(pjw, wjh, wjl, (long)E_*C_*H_);

    // 1) xn = rms(x); split
    rms_kernel<<<NTOK, 256>>>(x, xn);
    do_split(xn, xnh, xnl, (long)NTOK*C_);

    // 2) fused q/k/v projection (N = 2048)
    gemm_bf<<<dim3(QS/256, NTOK/128, 1), 256, SMEM>>>(
        (cus)xnh, (cus)xnl, 0, (cus)wqkvh, (cus)wqkvl, 0,
        qkv, nullptr, nullptr, 0, nullptr, NTOK, QS, C_, nullptr, nullptr, 0);

    // 3) gate + v update + rope + q/k rms
    gate_rope_kernel<<<NTOK, 256>>>(ve, cosb, sinb, gw);

    // 3b) attention prep: bf16 hi/lo Q (scaled), K, V^T
    q_prep_kernel<<<(B_*T_*NH*32)/256, 256>>>();
    k_prep_kernel<<<(B_*T_*NKV*32)/256, 256>>>();
    vt_prep_kernel<<<dim3(T_/64, NKV, B_), 256>>>();

    // 4) tensor-core attention (fixed max)
    attn_tc<<<dim3(T_/64, NH, B_), 128, ASMEM>>>(wptr);

    // 5) x1 = x + y @ c_proj^T
    do_split(y, yh, yl, (long)NTOK*C_);
    gemm_bf<<<dim3(C_/256, NTOK/128, 1), 256, SMEM>>>(
        (cus)yh, (cus)yl, 0, (cus)wph, (cus)wpl, 0,
        x1, nullptr, nullptr, 0, x, NTOK, C_, C_, nullptr, nullptr, 1);
    // 6) xn2 = rms(x1); split
    rms_kernel<<<NTOK, 256>>>(x1, xn2);
    do_split(xn2, xn2h, xn2l, (long)NTOK*C_);
    // 7) router softmax + top-2 (fp32 exact; writes rw output region)
    router_kernel<<<NTOK, 256>>>(rww, out + (long)NTOK * C_);
    // 8) stable dispatch
    route_kernel<<<1, 256>>>();
    // 9) h = relu(xn2[gather] @ fc_w[e]^T)^2  -> split bf16 out
    gemm_bf<<<dim3(H_/256, CAP/128, E_), 256, SMEM>>>(
        (cus)xn2h, (cus)xn2l, 0, (cus)wfh, (cus)wfl, (long)H_*C_,
        nullptr, (unsigned*)hh, (unsigned*)hl, (long)CAP*H_, nullptr,
        CAP, H_, C_, rowsrc, me, 2);
    // 10) bo = h @ proj_w[e]^T
    gemm_bf<<<dim3(C_/256, CAP/128, E_), 256, SMEM>>>(
        (cus)hh, (cus)hl, (long)CAP*H_, (cus)wjh, (cus)wjl, (long)C_*H_,
        bo, nullptr, nullptr, (long)CAP*C_, nullptr,
        CAP, C_, H_, nullptr, me, 0);
    // 11) final combine -> x output region
    combine_kernel<<<NTOK, 256>>>(out);
}